// round 9
// baseline (speedup 1.0000x reference)
#include <cuda_runtime.h>
#include <cuda_bf16.h>
#include <cstdint>

// ---------------- constants ----------------
#define BATCH 4
#define T_TOTAL 35968706LL          // sum of all hypernet parameter counts
#define T2 (T_TOTAL / 2)            // 17,984,353 float2 columns (T_TOTAL is even)

// Persistent grid: 2 blocks/SM x 148 SMs. __launch_bounds__(256,2) gives regs<=128
// (actual ~45), so co-residency of all 296 blocks is unconditional (0 smem, 512 thr/SM).
#define NBLK 296
#define NTHR (NBLK * 256)           // 75,776 persistent threads

// ---------------- device scratch (no allocation allowed) ----------------
__device__ float g_bufA[4 * 4 * 112 * 112];   // 200,704 floats
__device__ float g_bufB[4 * 8 * 56 * 56];     // 100,352 floats
__device__ float g_q[BATCH * 16];             // quantized latents for the big GEMM

// ---------------- software grid barrier (sense-reversal, replay-safe) ----------------
__device__ unsigned g_count = 0;
__device__ unsigned g_sense = 0;

__device__ __forceinline__ void grid_barrier(unsigned& local_sense) {
    __threadfence();                 // make this block's writes GPU-visible
    __syncthreads();
    if (threadIdx.x == 0) {
        local_sense += 1;
        unsigned arrived = atomicAdd(&g_count, 1u) + 1u;
        if (arrived == NBLK) {
            g_count = 0;
            __threadfence();
            atomicExch(&g_sense, local_sense);   // release
        } else {
            while ((int)(atomicAdd(&g_sense, 0u) - local_sense) < 0) { __nanosleep(64); }
            __threadfence();                      // acquire
        }
    } else {
        local_sense += 1;            // keep all threads' sense in sync
    }
    __syncthreads();
}

// ---------------- conv stage: 4x4 stride-2 pad-1, grid-stride, full unroll ----------
// SPLIT > 1: Cin reduction split across SPLIT adjacent lanes, reduced by shuffle.
// Every stage TOTAL is a multiple of 32, and NTHR is a multiple of 32, so the
// validity boundary never splits a warp -> shuffles stay converged.
template<int CIN, int COUT, int HIN, int HOUT, bool ACT, int SPLIT>
__device__ __forceinline__ void conv_stage(const float* __restrict__ in,
                                           const float* __restrict__ w,
                                           const float* __restrict__ bias,
                                           float* __restrict__ out) {
    constexpr int CPS = CIN / SPLIT;
    constexpr int TOTAL = BATCH * COUT * HOUT * HOUT * SPLIT;
    constexpr int ITERS = (TOTAL + NTHR - 1) / NTHR;
    int gtid = blockIdx.x * 256 + threadIdx.x;

    #pragma unroll 1
    for (int it = 0; it < ITERS; it++) {
        int tid = gtid + it * NTHR;
        bool valid = tid < TOTAL;
        int id = valid ? tid : 0;     // clamp; invalid lanes compute garbage, don't store

        int s = id % SPLIT;
        int o = id / SPLIT;
        int ow = o % HOUT;
        int oh = (o / HOUT) % HOUT;
        int co = (o / (HOUT * HOUT)) % COUT;
        int b  = o / (HOUT * HOUT * COUT);

        float acc = 0.0f;
        int ih0 = oh * 2 - 1;
        int iw0 = ow * 2 - 1;

        const float* wbase = w + ((size_t)co * CIN + s * CPS) * 16;
        const float* ibase = in + ((size_t)b * CIN + s * CPS) * HIN * HIN;

        #pragma unroll
        for (int ci = 0; ci < CPS; ci++) {
            const float* ip = ibase + (size_t)ci * HIN * HIN;
            const float* wp = wbase + ci * 16;
            #pragma unroll
            for (int kh = 0; kh < 4; kh++) {
                int ih = ih0 + kh;
                bool rowok = (unsigned)ih < (unsigned)HIN;
                #pragma unroll
                for (int kw = 0; kw < 4; kw++) {
                    int iw = iw0 + kw;
                    bool ok = rowok && ((unsigned)iw < (unsigned)HIN);
                    float v = ok ? __ldg(ip + (size_t)ih * HIN + iw) : 0.0f;
                    acc = fmaf(v, __ldg(wp + kh * 4 + kw), acc);
                }
            }
        }

        #pragma unroll
        for (int off = SPLIT / 2; off > 0; off >>= 1)
            acc += __shfl_xor_sync(0xffffffffu, acc, off);

        if (valid && s == 0) {
            acc += bias[co];
            if (ACT) acc = (acc >= 0.0f) ? acc : 0.01f * acc;
            out[o] = acc;
        }
    }
}

// ---------------- fused encoder: 5 convs + head, one launch ----------------
__global__ void __launch_bounds__(256, 2) encoder_fused(
    const float* __restrict__ rgb,
    const float* __restrict__ cw1, const float* __restrict__ cb1,
    const float* __restrict__ cw2, const float* __restrict__ cb2,
    const float* __restrict__ cw3, const float* __restrict__ cb3,
    const float* __restrict__ cw4, const float* __restrict__ cb4,
    const float* __restrict__ cw5, const float* __restrict__ cb5,
    const float* __restrict__ fc1_w, const float* __restrict__ fc1_b,
    const float* __restrict__ fc2_w, const float* __restrict__ fc2_b,
    const float* __restrict__ emb,
    float* __restrict__ loss_out) {

    unsigned local_sense = *(volatile unsigned*)&g_sense;   // snapshot (replay-safe)

    conv_stage<3, 4, 224, 112, true, 1>(rgb, cw1, cb1, g_bufA);
    grid_barrier(local_sense);
    conv_stage<4, 8, 112, 56, true, 1>(g_bufA, cw2, cb2, g_bufB);
    grid_barrier(local_sense);
    conv_stage<8, 16, 56, 28, true, 4>(g_bufB, cw3, cb3, g_bufA);
    grid_barrier(local_sense);
    conv_stage<16, 32, 28, 14, true, 4>(g_bufA, cw4, cb4, g_bufB);
    grid_barrier(local_sense);
    conv_stage<32, 64, 14, 7, false, 8>(g_bufB, cw5, cb5, g_bufA);
    grid_barrier(local_sense);

    // head on block 0 only: pool + fc1 + fc2 + VQ + loss
    if (blockIdx.x == 0) {
        __shared__ float pooled[BATCH * 64];
        __shared__ float h[BATCH * 16];
        __shared__ float e[BATCH * 16];
        __shared__ float qv[BATCH * 16];
        int tid = threadIdx.x;   // 256 threads
        const float* conv5 = g_bufA;

        {
            int b = tid / 64, c = tid % 64;
            const float* p = conv5 + (size_t)(b * 64 + c) * 49;
            float sum = 0.0f;
            #pragma unroll
            for (int i = 0; i < 49; i++) sum += p[i];
            pooled[b * 64 + c] = sum * (1.0f / 49.0f);
        }
        __syncthreads();

        if (tid < 64) {
            int b = tid / 16, i = tid % 16;
            float s = fc1_b[i];
            #pragma unroll
            for (int c = 0; c < 64; c++) s += pooled[b * 64 + c] * fc1_w[i * 64 + c];
            h[b * 16 + i] = (s >= 0.0f) ? s : 0.01f * s;
        }
        __syncthreads();

        if (tid < 64) {
            int b = tid / 16, j = tid % 16;
            float s = fc2_b[j];
            #pragma unroll
            for (int i = 0; i < 16; i++) s += h[b * 16 + i] * fc2_w[j * 16 + i];
            e[b * 16 + j] = s;
        }
        __syncthreads();

        if (tid < BATCH) {
            int b = tid;
            float best = 3.402823e38f;
            int bi = 0;
            for (int j = 0; j < 4; j++) {
                float d = 0.0f;
                #pragma unroll
                for (int k = 0; k < 16; k++) {
                    float diff = e[b * 16 + k] - emb[j * 16 + k];
                    d += diff * diff;
                }
                if (d < best) { best = d; bi = j; }
            }
            #pragma unroll
            for (int k = 0; k < 16; k++) qv[b * 16 + k] = emb[bi * 16 + k];
        }
        __syncthreads();

        if (tid == 0) {
            float s = 0.0f;
            #pragma unroll
            for (int n = 0; n < 64; n++) {
                float d = qv[n] - e[n];
                s += d * d;
            }
            *loss_out = 1.25f * (s * (1.0f / 64.0f));   // q_lat + 0.25 * e_lat
            #pragma unroll
            for (int n = 0; n < 64; n++) g_q[n] = qv[n];
        }
    }
}

// ---------------- big GEMM: flat = q @ W_all, [4,16] x [16, T_TOTAL] ----------------
// Pure HBM streaming, float2 vectorized, streaming cache hints. Proven R7 config.
__global__ void __launch_bounds__(256) hyper_gemm_k(const float* __restrict__ W,
                                                    float* __restrict__ out) {
    __shared__ float qs[64];
    if (threadIdx.x < 64) qs[threadIdx.x] = g_q[threadIdx.x];
    __syncthreads();

    long long t2 = (long long)blockIdx.x * blockDim.x + threadIdx.x;
    if (t2 >= T2) return;

    float2 w[16];
    #pragma unroll
    for (int k = 0; k < 16; k++) {
        w[k] = __ldcs((const float2*)(W + (size_t)k * T_TOTAL) + t2);
    }

    #pragma unroll
    for (int b = 0; b < 4; b++) {
        float ax = 0.0f, ay = 0.0f;
        #pragma unroll
        for (int k = 0; k < 16; k++) {
            float qk = qs[b * 16 + k];
            ax = fmaf(qk, w[k].x, ax);
            ay = fmaf(qk, w[k].y, ay);
        }
        __stcs((float2*)(out + (size_t)b * T_TOTAL) + t2, make_float2(ax, ay));
    }
}

// ---------------- launch ----------------
extern "C" void kernel_launch(void* const* d_in, const int* in_sizes, int n_in,
                              void* d_out, int out_size) {
    const float* rgb   = (const float*)d_in[0];
    const float* cw1   = (const float*)d_in[1];
    const float* cb1   = (const float*)d_in[2];
    const float* cw2   = (const float*)d_in[3];
    const float* cb2   = (const float*)d_in[4];
    const float* cw3   = (const float*)d_in[5];
    const float* cb3   = (const float*)d_in[6];
    const float* cw4   = (const float*)d_in[7];
    const float* cb4   = (const float*)d_in[8];
    const float* cw5   = (const float*)d_in[9];
    const float* cb5   = (const float*)d_in[10];
    const float* fc1_w = (const float*)d_in[11];
    const float* fc1_b = (const float*)d_in[12];
    const float* fc2_w = (const float*)d_in[13];
    const float* fc2_b = (const float*)d_in[14];
    const float* emb   = (const float*)d_in[15];
    const float* W_all = (const float*)d_in[16];

    float* out = (float*)d_out;
    float* loss_ptr = out + (size_t)out_size - 1;   // flat first, loss scalar last

    // single fused encoder launch (5 convs + head)
    encoder_fused<<<NBLK, 256>>>(rgb, cw1, cb1, cw2, cb2, cw3, cb3, cw4, cb4,
                                 cw5, cb5, fc1_w, fc1_b, fc2_w, fc2_b, emb, loss_ptr);

    // big streaming GEMM: flat = q @ W_all
    { const int TPB = 256;
      long long nblk = (T2 + TPB - 1) / TPB;
      hyper_gemm_k<<<(unsigned)nblk, TPB>>>(W_all, out); }
}